// round 11
// baseline (speedup 1.0000x reference)
#include <cuda_runtime.h>
#include <cuda_bf16.h>
#include <math_constants.h>

#define BQ 64
#define LQ 32
#define BD 128
#define LD 192
#define TOK_D 32
#define CLS_D 768

// 256-slot hash of doc token ids. Chains are LIFO lists; entry index == doc
// position j, so an entry only stores (id << 8 | next_index).
__device__ __forceinline__ unsigned hash_id(unsigned id) {
    return (id * 0x9E3779B1u) >> 24;   // 0..255
}

// ---------------------------------------------------------------------------
// One kernel, one pass. Block = (doc d, half of the queries), 256 threads.
// grid = 256. Warp w handles queries qbase + 4w..4w+3; lane = query pos i.
//   pre-barrier:  clear slots | insert 192 doc ids | CLS dots (L2 LDG-heavy)
//   post-barrier: hash walk -> rare 32-dim dots from L2 -> mask -> butterfly
// ---------------------------------------------------------------------------
__global__ __launch_bounds__(256) void coil_hash_kernel(
    const float* __restrict__ qtok,   // [BQ, LQ, TOK_D]
    const float* __restrict__ dtok,   // [BD, LD, TOK_D]
    const float* __restrict__ qcls,   // [BQ, CLS_D]
    const float* __restrict__ dcls,   // [BD, CLS_D]
    const int*   __restrict__ qids,   // [BQ, LQ]
    const int*   __restrict__ dids,   // [BD, LD]
    const int*   __restrict__ qmask,  // [BQ, LQ]
    float*       __restrict__ out)    // [BQ, BD]
{
    __shared__ unsigned slots[256];   // head index per bucket, 0xFF = empty
    __shared__ unsigned ent[LD];      // (id << 8) | next_index

    const int bx    = blockIdx.x;
    const int d     = bx >> 1;
    const int qbase = (bx & 1) * 32;
    const int t     = threadIdx.x;
    const int w     = t >> 5;         // 0..7
    const int lane  = t & 31;

    // ---- prefetch (pure LDG, no smem dependence) ----
    int qid4[4], qm4[4];
#pragma unroll
    for (int k = 0; k < 4; k++) {
        const int q = qbase + w * 4 + k;
        qid4[k] = qids[q * LQ + lane];
        qm4[k]  = qmask[q * LQ + lane];
    }
    unsigned myid = 0u;
    if (t < LD) myid = (unsigned)dids[d * LD + t];

    slots[t] = 0xFFFFFFFFu;
    __syncthreads();                  // slots clear visible before inserts

    // ---- build hash table (entry index == doc position j) ----
    if (t < LD) {
        const unsigned h = hash_id(myid);
        const unsigned old = atomicExch(&slots[h], (unsigned)t);
        ent[t] = (myid << 8) | (old & 0xFFu);
    }

    // ---- CLS dots, fully overlapped with table build ----
    float4 bv[6];
#pragma unroll
    for (int c = 0; c < 6; c++)
        bv[c] = ((const float4*)(dcls + d * CLS_D))[c * 32 + lane];
    float cls4[4];
#pragma unroll
    for (int k = 0; k < 4; k++) {
        const int q = qbase + w * 4 + k;
        const float4* qc = (const float4*)(qcls + q * CLS_D);
        float acc = 0.0f;
#pragma unroll
        for (int c = 0; c < 6; c++) {
            const float4 a = qc[c * 32 + lane];
            acc += a.x * bv[c].x + a.y * bv[c].y + a.z * bv[c].z + a.w * bv[c].w;
        }
        cls4[k] = acc;
    }
    __syncthreads();                  // table complete

    // ---- lookup + combine ----
    float v[4];
#pragma unroll
    for (int k = 0; k < 4; k++) {
        const int q = qbase + w * 4 + k;
        const unsigned qid = (unsigned)qid4[k];

        const int tot = __reduce_add_sync(0xFFFFFFFFu, qm4[k]);
        const float qmf = (lane == tot - 1) ? 0.0f : (float)qm4[k];

        float m = -CUDART_INF_F;
        int cnt = 0;
        unsigned cur = slots[hash_id(qid)] & 0xFFu;
        while (cur != 0xFFu) {
            const unsigned e = ent[cur];
            if ((e >> 8) == qid) {
                const float4* qr = (const float4*)(qtok + (q * LQ + lane) * TOK_D);
                const float4* dr = (const float4*)(dtok + (d * LD + (int)cur) * TOK_D);
                float s = 0.0f;
#pragma unroll
                for (int e2 = 0; e2 < TOK_D / 4; e2++) {
                    const float4 a = qr[e2];
                    const float4 b = dr[e2];
                    s += a.x * b.x + a.y * b.y + a.z * b.z + a.w * b.w;
                }
                m = fmaxf(m, s);
                cnt++;
            }
            cur = e & 0xFFu;
        }
        // where(match, s, 0).max over j: zeros participate unless ALL 192 match
        const float val = (cnt == 0) ? 0.0f : ((cnt < LD) ? fmaxf(m, 0.0f) : m);
        v[k] = ((lane >= 1) ? val * qmf : 0.0f) + cls4[k];
    }

#pragma unroll
    for (int s = 16; s; s >>= 1) {
#pragma unroll
        for (int k = 0; k < 4; k++) v[k] += __shfl_xor_sync(0xFFFFFFFFu, v[k], s);
    }
    if (lane == 0) {
#pragma unroll
        for (int k = 0; k < 4; k++) out[(qbase + w * 4 + k) * BD + d] = v[k];
    }
}

// ---------------------------------------------------------------------------
extern "C" void kernel_launch(void* const* d_in, const int* in_sizes, int n_in,
                              void* d_out, int out_size) {
    const float* qtok  = (const float*)d_in[0];
    const float* dtok  = (const float*)d_in[1];
    const float* qcls  = (const float*)d_in[2];
    const float* dcls  = (const float*)d_in[3];
    const int*   qids  = (const int*)d_in[4];
    const int*   dids  = (const int*)d_in[5];
    const int*   qmask = (const int*)d_in[6];
    float* out = (float*)d_out;

    coil_hash_kernel<<<2 * BD, 256>>>(qtok, dtok, qcls, dcls, qids, dids, qmask, out);
}

// round 13
// speedup vs baseline: 1.1152x; 1.1152x over previous
#include <cuda_runtime.h>
#include <cuda_bf16.h>
#include <math_constants.h>

#define BQ 64
#define LQ 32
#define BD 128
#define LD 192
#define TOK_D 32
#define CLS_D 768

// Order-preserving uint encoding of float (monotonic for all finite values)
__device__ __forceinline__ unsigned enc_f(float f) {
    unsigned b = __float_as_uint(f);
    return (b & 0x80000000u) ? ~b : (b | 0x80000000u);
}
__device__ __forceinline__ float dec_f(unsigned u) {
    return __uint_as_float((u & 0x80000000u) ? (u ^ 0x80000000u) : ~u);
}

__device__ __forceinline__ unsigned hash_id(unsigned id) {
    return (id * 0x9E3779B1u) >> 20;   // 0..4095
}

// ---------------------------------------------------------------------------
// One kernel. Block = doc d (128 blocks x 512 threads).
//  seg 1: init slots/mslot, stage dcls, prefetch qids/qmask/doc ids   [LDG]
//  seg 2: build hash of all 2048 query (q,i) ids  ||  CLS dots        [ATOMS/LDG]
//  seg 3: 192 doc tokens probe the hash; matches do 32-dim dot from L2
//         and atomicMax an order-independent slot                      [LDS/LDG]
//  seg 4: per warp: 4 queries -> slots + mask + CLS, butterfly, store
// ---------------------------------------------------------------------------
__global__ __launch_bounds__(512) void coil_probe_kernel(
    const float* __restrict__ qtok,   // [BQ, LQ, TOK_D]
    const float* __restrict__ dtok,   // [BD, LD, TOK_D]
    const float* __restrict__ qcls,   // [BQ, CLS_D]
    const float* __restrict__ dcls,   // [BD, CLS_D]
    const int*   __restrict__ qids,   // [BQ, LQ]
    const int*   __restrict__ dids,   // [BD, LD]
    const int*   __restrict__ qmask,  // [BQ, LQ]
    float*       __restrict__ out)    // [BQ, BD]
{
    __shared__ unsigned slots[4096];  // 16 KB: head entry per bucket, 0xFFF empty
    __shared__ unsigned ent[BQ * LQ]; // 8 KB: (id << 12) | next
    __shared__ unsigned mslot[BQ * LQ]; // 8 KB: enc-float max per (q,i)
    __shared__ float    dclsS[CLS_D]; // 3 KB
    __shared__ int      allsameS;

    const int d    = blockIdx.x;
    const int t    = threadIdx.x;
    const int w    = t >> 5;
    const int lane = t & 31;

    // ---- prefetch (pure LDG, no smem dependence) ----
    int qid4[4], qm4[4];
#pragma unroll
    for (int k = 0; k < 4; k++) {
        const int q = w * 4 + k;
        qid4[k] = qids[q * LQ + lane];
        qm4[k]  = qmask[q * LQ + lane];
    }
    unsigned bid[4];                            // ids for hash build (coalesced)
#pragma unroll
    for (int f = 0; f < 4; f++) bid[f] = (unsigned)qids[t + f * 512];

    unsigned myid = 0u;
    if (t < LD) myid = (unsigned)dids[d * LD + t];
    const unsigned d0id = (unsigned)dids[d * LD];   // for the all-match corner

    // ---- seg 1: init ----
#pragma unroll
    for (int f = 0; f < 8; f++) slots[t + f * 512] = 0xFFFu;
#pragma unroll
    for (int f = 0; f < 4; f++) mslot[t + f * 512] = 0u;
    if (t < CLS_D / 4) ((float4*)dclsS)[t] = ((const float4*)(dcls + d * CLS_D))[t];
    if (t == 0) allsameS = 1;
    __syncthreads();

    // ---- seg 2a: build query-id hash (entry index == q*32 + i) ----
#pragma unroll
    for (int f = 0; f < 4; f++) {
        const unsigned e  = (unsigned)(t + f * 512);
        const unsigned h  = hash_id(bid[f]);
        const unsigned old = atomicExch(&slots[h], e);
        ent[e] = (bid[f] << 12) | (old & 0xFFFu);
    }
    if (t < LD && myid != d0id) allsameS = 0;

    // ---- seg 2b: CLS dots (overlaps hash build; LDG-heavy) ----
    float4 bv[6];
#pragma unroll
    for (int c = 0; c < 6; c++) bv[c] = ((const float4*)dclsS)[c * 32 + lane];
    float cls4[4];
#pragma unroll
    for (int k = 0; k < 4; k++) {
        const int q = w * 4 + k;
        const float4* qc = (const float4*)(qcls + q * CLS_D);
        float acc = 0.0f;
#pragma unroll
        for (int c = 0; c < 6; c++) {
            const float4 a = qc[c * 32 + lane];
            acc += a.x * bv[c].x + a.y * bv[c].y + a.z * bv[c].z + a.w * bv[c].w;
        }
        cls4[k] = acc;
    }
    __syncthreads();                  // hash table complete

    // ---- seg 3: doc tokens probe; matches dot + atomicMax ----
    if (t < LD) {
        const float4* dr = (const float4*)(dtok + (d * LD + t) * TOK_D);
        float4 dv[8];
        bool loaded = false;
        unsigned cur = slots[hash_id(myid)];
        while (cur != 0xFFFu) {
            const unsigned e = ent[cur];
            if ((e >> 12) == myid) {
                if (!loaded) {
#pragma unroll
                    for (int i = 0; i < 8; i++) dv[i] = dr[i];
                    loaded = true;
                }
                const float4* qr = (const float4*)(qtok + cur * TOK_D);
                float s = 0.0f;
#pragma unroll
                for (int i = 0; i < 8; i++) {
                    const float4 a = qr[i];
                    s += a.x * dv[i].x + a.y * dv[i].y + a.z * dv[i].z + a.w * dv[i].w;
                }
                atomicMax(&mslot[cur], enc_f(s));
            }
            cur = e & 0xFFFu;
        }
    }
    __syncthreads();                  // all maxes landed

    // ---- seg 4: per-query combine + butterfly + store ----
    float v[4];
#pragma unroll
    for (int k = 0; k < 4; k++) {
        const int q = w * 4 + k;
        const int tot = __reduce_add_sync(0xFFFFFFFFu, qm4[k]);
        const float qmf = (lane == tot - 1) ? 0.0f : (float)qm4[k];

        const unsigned slot = mslot[q * LQ + lane];
        float val;
        if (slot == 0u) {
            val = 0.0f;               // no match: row of zeros -> max is 0
        } else {
            const float mm = dec_f(slot);
            // all 192 doc tokens match this id -> no zero participates in max
            const bool full = allsameS && ((unsigned)qid4[k] == d0id);
            val = full ? mm : fmaxf(mm, 0.0f);
        }
        v[k] = ((lane >= 1) ? val * qmf : 0.0f) + cls4[k];
    }
#pragma unroll
    for (int s = 16; s; s >>= 1) {
#pragma unroll
        for (int k = 0; k < 4; k++) v[k] += __shfl_xor_sync(0xFFFFFFFFu, v[k], s);
    }
    if (lane == 0) {
#pragma unroll
        for (int k = 0; k < 4; k++) out[(w * 4 + k) * BD + d] = v[k];
    }
}

// ---------------------------------------------------------------------------
extern "C" void kernel_launch(void* const* d_in, const int* in_sizes, int n_in,
                              void* d_out, int out_size) {
    const float* qtok  = (const float*)d_in[0];
    const float* dtok  = (const float*)d_in[1];
    const float* qcls  = (const float*)d_in[2];
    const float* dcls  = (const float*)d_in[3];
    const int*   qids  = (const int*)d_in[4];
    const int*   dids  = (const int*)d_in[5];
    const int*   qmask = (const int*)d_in[6];
    float* out = (float*)d_out;

    coil_probe_kernel<<<BD, 512>>>(qtok, dtok, qcls, dcls, qids, dids, qmask, out);
}